// round 6
// baseline (speedup 1.0000x reference)
#include <cuda_runtime.h>
#include <cuda_fp16.h>
#include <cstdint>

#define NN  50000
#define EE  800000
#define FIN 128
#define KK  32
#define NB_SCAN ((NN + 1023) / 1024)
#define AS  136   // smem tile stride in fp16 elems (128 + 8 pad)

typedef unsigned long long u64;

// ---------------- device scratch (no allocations allowed) ----------------
__device__ float g_xs[(size_t)NN * FIN];    // dense MaxK-sparsified features
__device__ float g_agg[(size_t)NN * FIN];   // normalized neighbor aggregate
__device__ int   g_deg[NN];
__device__ int   g_off[NN + 1];
__device__ int   g_cur[NN];
__device__ int   g_bsum[64];
__device__ int   g_csr[EE];                 // src ids grouped by dst
// Pre-built fp16 MMA B fragments: [ph][kstep(8)][wcol(2)][lane(32)][16]
__device__ uint32_t g_bf[2][8][2][32][16];

// ---------------- PTX helpers (baseline sm_80-class only) ----------------
__device__ __forceinline__ uint32_t smem_u32(const void* p) {
    uint32_t a;
    asm("{ .reg .u64 t; cvta.to.shared.u64 t, %1; cvt.u32.u64 %0, t; }" : "=r"(a) : "l"(p));
    return a;
}
__device__ __forceinline__ void ldm_x4(uint32_t* r, uint32_t addr) {
    asm volatile("ldmatrix.sync.aligned.m8n8.x4.shared.b16 {%0,%1,%2,%3}, [%4];"
                 : "=r"(r[0]), "=r"(r[1]), "=r"(r[2]), "=r"(r[3]) : "r"(addr));
}
__device__ __forceinline__ void mma_fp16(float* c, const uint32_t* a, uint32_t b0, uint32_t b1) {
    asm volatile(
        "mma.sync.aligned.m16n8k16.row.col.f32.f16.f16.f32 "
        "{%0,%1,%2,%3}, {%4,%5,%6,%7}, {%8,%9}, {%0,%1,%2,%3};"
        : "+f"(c[0]), "+f"(c[1]), "+f"(c[2]), "+f"(c[3])
        : "r"(a[0]), "r"(a[1]), "r"(a[2]), "r"(a[3]), "r"(b0), "r"(b1));
}
// ldmatrix.x4 address for a 16x16 tile at (row, col) in a [128][AS] fp16 tile
__device__ __forceinline__ uint32_t ldm_addr(uint32_t base, int row, int col, int lane) {
    int r = row + (lane & 15);
    int c = col + ((lane >> 4) << 3);
    return base + (uint32_t)((r * AS + c) * 2);
}

// ---------------- small kernels ----------------

__global__ void deg_kernel(const int* __restrict__ dst) {
    int e = blockIdx.x * blockDim.x + threadIdx.x;
    if (e < EE) atomicAdd(&g_deg[dst[e]], 1);
}

// phase 1: per-1024 chunk local exclusive scan -> g_off, chunk totals -> g_bsum
__global__ void scan1_kernel() {
    __shared__ int wsum[32];
    int t = threadIdx.x, lane = t & 31, wid = t >> 5;
    int i = blockIdx.x * 1024 + t;
    int v = (i < NN) ? g_deg[i] : 0;
    int s = v;
    #pragma unroll
    for (int off = 1; off < 32; off <<= 1) {
        int x = __shfl_up_sync(0xffffffffu, s, off);
        if (lane >= off) s += x;
    }
    if (lane == 31) wsum[wid] = s;
    __syncthreads();
    if (wid == 0) {
        int ws = wsum[lane];
        int sc = ws;
        #pragma unroll
        for (int off = 1; off < 32; off <<= 1) {
            int x = __shfl_up_sync(0xffffffffu, sc, off);
            if (lane >= off) sc += x;
        }
        wsum[lane] = sc - ws;
        if (lane == 31) g_bsum[blockIdx.x] = sc;
    }
    __syncthreads();
    if (i < NN) g_off[i] = wsum[wid] + s - v;
}

// phase 2: one warp exclusively scans the chunk totals in place.
__global__ void scan2_kernel() {
    int lane = threadIdx.x;
    int carry = 0;
    for (int base = 0; base < NB_SCAN; base += 32) {
        int i = base + lane;
        int v = (i < NB_SCAN) ? g_bsum[i] : 0;
        if (i == NB_SCAN - 1) g_off[NN] = v;
        int s = v;
        #pragma unroll
        for (int off = 1; off < 32; off <<= 1) {
            int x = __shfl_up_sync(0xffffffffu, s, off);
            if (lane >= off) s += x;
        }
        if (i < NB_SCAN) g_bsum[i] = carry + s - v;
        carry += __shfl_sync(0xffffffffu, s, 31);
    }
}

__global__ void scatter_kernel(const int* __restrict__ src, const int* __restrict__ dst) {
    int e = blockIdx.x * blockDim.x + threadIdx.x;
    if (e < EE) {
        int d = dst[e];
        int p = atomicAdd(&g_cur[d], 1);
        g_csr[g_off[d] + g_bsum[d >> 10] + p] = src[e];
    }
}

// Dense x_sparse rows; last-wins duplicate semantics.
__global__ void xs_kernel(const float* __restrict__ tv, const int* __restrict__ ti) {
    __shared__ int   sidx[8][32];
    __shared__ float sval[8][32];
    int w = threadIdx.x >> 5, lane = threadIdx.x & 31;
    int row = blockIdx.x * 8 + w;
    if (row >= NN) return;
    sidx[w][lane] = ti[row * KK + lane];
    sval[w][lane] = tv[row * KK + lane];
    __syncwarp();
    float r0 = 0.f, r1 = 0.f, r2 = 0.f, r3 = 0.f;
    #pragma unroll
    for (int j = 0; j < 32; j++) {
        int c = sidx[w][j];
        float v = sval[w][j];
        if ((c >> 2) == lane) {
            int sub = c & 3;
            if      (sub == 0) r0 = v;
            else if (sub == 1) r1 = v;
            else if (sub == 2) r2 = v;
            else               r3 = v;
        }
    }
    *(float4*)&g_xs[(size_t)row * FIN + lane * 4] = make_float4(r0, r1, r2, r3);
}

// One warp per dst node: sum dense x_sparse rows of its neighbors.
__global__ void agg_kernel() {
    int gw = (blockIdx.x * blockDim.x + threadIdx.x) >> 5;
    int lane = threadIdx.x & 31;
    if (gw >= NN) return;
    int start = g_off[gw] + g_bsum[gw >> 10];
    int end   = g_off[gw + 1] + g_bsum[(gw + 1) >> 10];
    float4 acc = make_float4(0.f, 0.f, 0.f, 0.f);
    for (int chunk = start; chunk < end; chunk += 32) {
        int i = chunk + lane;
        int s = (i < end) ? g_csr[i] : 0;
        int m = min(32, end - chunk);
        for (int j = 0; j < m; j++) {
            int ss = __shfl_sync(0xffffffffu, s, j);
            const float4 x = *(const float4*)&g_xs[(size_t)ss * FIN + lane * 4];
            acc.x += x.x; acc.y += x.y; acc.z += x.z; acc.w += x.w;
        }
    }
    int deg = end - start;
    float wgt = 1.0f / (float)max(deg, 1);
    acc.x *= wgt; acc.y *= wgt; acc.z *= wgt; acc.w *= wgt;
    *(float4*)&g_agg[(size_t)gw * FIN + lane * 4] = acc;
}

// Build per-thread fp16 MMA B fragments from W (row-major [k][n]).
// Element for (ph, ks, wc, lane, nf, r):
//   k = ks*16 + (lane%4)*2 + r*8, n = wc*64 + nf*8 + lane/4, pair (k, k+1).
__global__ void wprep_kernel(const float* __restrict__ Ws, const float* __restrict__ Wn) {
    int idx = blockIdx.x * 256 + threadIdx.x;   // 0..16383
    int j    = idx & 15;
    int lane = (idx >> 4) & 31;
    int wc   = (idx >> 9) & 1;
    int ks   = (idx >> 10) & 7;
    int ph   = (idx >> 13) & 1;
    int nf = j >> 1, r = j & 1;
    int k = ks * 16 + (lane & 3) * 2 + r * 8;
    int n = wc * 64 + nf * 8 + (lane >> 2);
    const float* W = ph ? Wn : Ws;
    __half2 outp = __floats2half2_rn(W[k * 128 + n], W[(k + 1) * 128 + n]);
    ((uint32_t*)g_bf)[idx] = *(uint32_t*)&outp;
}

// ---------------- single-pass fp16 HMMA GEMM ----------------
// out = [feat | agg] @ [[W_self],[W_neigh]] + b
// 128x128 CTA tile, 8 warps x (32 x 64), K in two 128-phases.
// A fp16 in smem (ldmatrix); B direct from prebuilt gmem fragments.

#define SM_TOTAL (128 * AS * 2)   // 34,816 bytes

__global__ void __launch_bounds__(256, 2) gemm_kernel(
    const float* __restrict__ feat,
    const float* __restrict__ bself,
    float* __restrict__ out)
{
    extern __shared__ char smem[];
    uint32_t sb = smem_u32(smem);
    const int t = threadIdx.x, w = t >> 5, lane = t & 31;
    const int rowBase = blockIdx.x * 128;
    const int wm = (w & 3) * 32;        // warp row offset in tile
    const int wc = w >> 2;              // warp col half (0/1)

    float acc[2][8][4];
    #pragma unroll
    for (int mf = 0; mf < 2; mf++)
        #pragma unroll
        for (int nf = 0; nf < 8; nf++)
            #pragma unroll
            for (int e = 0; e < 4; e++) acc[mf][nf][e] = 0.f;

    const int fr = t >> 1;      // fill row 0..127
    const int half = t & 1;     // fill col half

    #pragma unroll
    for (int ph = 0; ph < 2; ph++) {
        const float* Asrc = ph ? g_agg : feat;
        const int gr = rowBase + fr;
        const bool valid = gr < NN;

        if (ph) __syncthreads();   // protect smem reuse from previous phase

        // ---- A fill: fp32 -> fp16 into padded [128][AS] tile ----
        #pragma unroll 4
        for (int j = 0; j < 16; j++) {
            int c = half * 64 + j * 4;
            float4 v = valid ? *(const float4*)(Asrc + (size_t)gr * FIN + c)
                             : make_float4(0.f, 0.f, 0.f, 0.f);
            __half2 h01 = __floats2half2_rn(v.x, v.y);
            __half2 h23 = __floats2half2_rn(v.z, v.w);
            uint32_t o = (uint32_t)((fr * AS + c) * 2);
            *(__half2*)(smem + o)     = h01;
            *(__half2*)(smem + o + 4) = h23;
        }
        __syncthreads();

        // ---- MMA mainloop: 8 k-steps of 16 ----
        #pragma unroll
        for (int ks = 0; ks < 8; ks++) {
            const int kb = ks * 16;
            // B fragments: 64B contiguous per thread, L1/L2 resident
            uint32_t bfr[16];
            {
                const uint4* hp = (const uint4*)&g_bf[ph][ks][wc][lane][0];
                #pragma unroll
                for (int q = 0; q < 4; q++) *(uint4*)&bfr[q * 4] = hp[q];
            }
            uint32_t afr[2][4];
            #pragma unroll
            for (int mf = 0; mf < 2; mf++)
                ldm_x4(afr[mf], ldm_addr(sb, wm + mf * 16, kb, lane));
            #pragma unroll
            for (int mf = 0; mf < 2; mf++)
                #pragma unroll
                for (int nf = 0; nf < 8; nf++)
                    mma_fp16(acc[mf][nf], afr[mf], bfr[nf * 2], bfr[nf * 2 + 1]);
        }
    }

    // ---- epilogue: +bias, store ----
    const int wn = wc * 64;
    const int cg = (lane & 3) * 2;     // col pair within n-frag
    const int rr = lane >> 2;          // row within m-frag half
    #pragma unroll
    for (int mf = 0; mf < 2; mf++) {
        int r0 = rowBase + wm + mf * 16 + rr;
        int r1 = r0 + 8;
        #pragma unroll
        for (int nf = 0; nf < 8; nf++) {
            int col = wn + nf * 8 + cg;
            float b0 = __ldg(bself + col), b1 = __ldg(bself + col + 1);
            if (r0 < NN) {
                float2 o = make_float2(acc[mf][nf][0] + b0, acc[mf][nf][1] + b1);
                *(float2*)(out + (size_t)r0 * FIN + col) = o;
            }
            if (r1 < NN) {
                float2 o = make_float2(acc[mf][nf][2] + b0, acc[mf][nf][3] + b1);
                *(float2*)(out + (size_t)r1 * FIN + col) = o;
            }
        }
    }
}

// ---------------- launch ----------------
extern "C" void kernel_launch(void* const* d_in, const int* in_sizes, int n_in,
                              void* d_out, int out_size) {
    const float *feat = nullptr, *topkv = nullptr, *Wself = nullptr,
                *bself = nullptr, *Wneigh = nullptr;
    const int *topki = nullptr, *src = nullptr, *dst = nullptr;

    for (int i = 0; i < n_in; i++) {
        int s = in_sizes[i];
        const void* p = d_in[i];
        if (s == NN * FIN)       feat = (const float*)p;
        else if (s == NN * KK) { if (!topkv) topkv = (const float*)p; else topki = (const int*)p; }
        else if (s == EE)      { if (!src)   src   = (const int*)p;   else dst   = (const int*)p; }
        else if (s == 128*128) { if (!Wself) Wself = (const float*)p; else Wneigh = (const float*)p; }
        else if (s == 128)       bself = (const float*)p;
    }
    float* out = (float*)d_out;

    static void* p_deg = nullptr;
    static void* p_cur = nullptr;
    if (!p_deg) {
        cudaGetSymbolAddress(&p_deg, g_deg);
        cudaGetSymbolAddress(&p_cur, g_cur);
        cudaFuncSetAttribute(gemm_kernel, cudaFuncAttributeMaxDynamicSharedMemorySize, SM_TOTAL);
    }

    cudaMemsetAsync(p_deg, 0, NN * sizeof(int));
    cudaMemsetAsync(p_cur, 0, NN * sizeof(int));
    deg_kernel<<<(EE + 255) / 256, 256>>>(dst);
    scan1_kernel<<<NB_SCAN, 1024>>>();
    scan2_kernel<<<1, 32>>>();
    scatter_kernel<<<(EE + 255) / 256, 256>>>(src, dst);
    xs_kernel<<<(NN + 7) / 8, 256>>>(topkv, topki);
    wprep_kernel<<<64, 256>>>(Wself, Wneigh);
    agg_kernel<<<(NN + 7) / 8, 256>>>();
    gemm_kernel<<<(NN + 127) / 128, 256, SM_TOTAL>>>(feat, bself, out);
}

// round 7
// speedup vs baseline: 1.6210x; 1.6210x over previous
#include <cuda_runtime.h>
#include <cuda_fp16.h>
#include <cstdint>

#define NN  50000
#define EE  800000
#define FIN 128
#define KK  32
#define NB_SCAN ((NN + 1023) / 1024)
#define AS  136   // smem tile stride in fp16 elems (128 + 8 pad)

typedef unsigned long long u64;

// ---------------- device scratch (no allocations allowed) ----------------
__device__ __half g_xs[(size_t)NN * FIN];   // dense MaxK features, fp16
__device__ __half g_agg[(size_t)NN * FIN];  // normalized neighbor agg, fp16
__device__ int   g_deg[NN];
__device__ int   g_off[NN + 1];
__device__ int   g_cur[NN];
__device__ int   g_bsum[64];
__device__ int   g_csr[EE];                 // src ids grouped by dst
// Pre-built fp16 MMA B fragments: [ph][kstep(8)][wcol(2)][lane(32)][16]
__device__ uint32_t g_bf[2][8][2][32][16];

// ---------------- PTX helpers (baseline sm_80-class only) ----------------
__device__ __forceinline__ uint32_t smem_u32(const void* p) {
    uint32_t a;
    asm("{ .reg .u64 t; cvta.to.shared.u64 t, %1; cvt.u32.u64 %0, t; }" : "=r"(a) : "l"(p));
    return a;
}
__device__ __forceinline__ void ldm_x4(uint32_t* r, uint32_t addr) {
    asm volatile("ldmatrix.sync.aligned.m8n8.x4.shared.b16 {%0,%1,%2,%3}, [%4];"
                 : "=r"(r[0]), "=r"(r[1]), "=r"(r[2]), "=r"(r[3]) : "r"(addr));
}
__device__ __forceinline__ void mma_fp16(float* c, const uint32_t* a, uint32_t b0, uint32_t b1) {
    asm volatile(
        "mma.sync.aligned.m16n8k16.row.col.f32.f16.f16.f32 "
        "{%0,%1,%2,%3}, {%4,%5,%6,%7}, {%8,%9}, {%0,%1,%2,%3};"
        : "+f"(c[0]), "+f"(c[1]), "+f"(c[2]), "+f"(c[3])
        : "r"(a[0]), "r"(a[1]), "r"(a[2]), "r"(a[3]), "r"(b0), "r"(b1));
}
// ldmatrix.x4 address for a 16x16 tile at (row, col) in a [128][AS] fp16 tile
__device__ __forceinline__ uint32_t ldm_addr(uint32_t base, int row, int col, int lane) {
    int r = row + (lane & 15);
    int c = col + ((lane >> 4) << 3);
    return base + (uint32_t)((r * AS + c) * 2);
}

// ---------------- small kernels ----------------

__global__ void deg_kernel(const int* __restrict__ dst) {
    int e = blockIdx.x * blockDim.x + threadIdx.x;
    if (e < EE) atomicAdd(&g_deg[dst[e]], 1);
}

// phase 1: per-1024 chunk local exclusive scan -> g_off, chunk totals -> g_bsum
// also clears g_cur for the scatter pass.
__global__ void scan1_kernel() {
    __shared__ int wsum[32];
    int t = threadIdx.x, lane = t & 31, wid = t >> 5;
    int i = blockIdx.x * 1024 + t;
    int v = (i < NN) ? g_deg[i] : 0;
    if (i < NN) g_cur[i] = 0;
    int s = v;
    #pragma unroll
    for (int off = 1; off < 32; off <<= 1) {
        int x = __shfl_up_sync(0xffffffffu, s, off);
        if (lane >= off) s += x;
    }
    if (lane == 31) wsum[wid] = s;
    __syncthreads();
    if (wid == 0) {
        int ws = wsum[lane];
        int sc = ws;
        #pragma unroll
        for (int off = 1; off < 32; off <<= 1) {
            int x = __shfl_up_sync(0xffffffffu, sc, off);
            if (lane >= off) sc += x;
        }
        wsum[lane] = sc - ws;
        if (lane == 31) g_bsum[blockIdx.x] = sc;
    }
    __syncthreads();
    if (i < NN) g_off[i] = wsum[wid] + s - v;
}

// phase 2: one warp exclusively scans the chunk totals in place.
__global__ void scan2_kernel() {
    int lane = threadIdx.x;
    int carry = 0;
    for (int base = 0; base < NB_SCAN; base += 32) {
        int i = base + lane;
        int v = (i < NB_SCAN) ? g_bsum[i] : 0;
        if (i == NB_SCAN - 1) g_off[NN] = v;
        int s = v;
        #pragma unroll
        for (int off = 1; off < 32; off <<= 1) {
            int x = __shfl_up_sync(0xffffffffu, s, off);
            if (lane >= off) s += x;
        }
        if (i < NB_SCAN) g_bsum[i] = carry + s - v;
        carry += __shfl_sync(0xffffffffu, s, 31);
    }
}

__global__ void scatter_kernel(const int* __restrict__ src, const int* __restrict__ dst) {
    int e = blockIdx.x * blockDim.x + threadIdx.x;
    if (e < EE) {
        int d = dst[e];
        int p = atomicAdd(&g_cur[d], 1);
        g_csr[g_off[d] + g_bsum[d >> 10] + p] = src[e];
    }
}

// Dense x_sparse rows (fp16); last-wins duplicate semantics.
__global__ void xs_kernel(const float* __restrict__ tv, const int* __restrict__ ti) {
    __shared__ int   sidx[8][32];
    __shared__ float sval[8][32];
    int w = threadIdx.x >> 5, lane = threadIdx.x & 31;
    int row = blockIdx.x * 8 + w;
    if (row >= NN) return;
    sidx[w][lane] = ti[row * KK + lane];
    sval[w][lane] = tv[row * KK + lane];
    __syncwarp();
    float r0 = 0.f, r1 = 0.f, r2 = 0.f, r3 = 0.f;
    #pragma unroll
    for (int j = 0; j < 32; j++) {
        int c = sidx[w][j];
        float v = sval[w][j];
        if ((c >> 2) == lane) {
            int sub = c & 3;
            if      (sub == 0) r0 = v;
            else if (sub == 1) r1 = v;
            else if (sub == 2) r2 = v;
            else               r3 = v;
        }
    }
    __half2 h01 = __floats2half2_rn(r0, r1);
    __half2 h23 = __floats2half2_rn(r2, r3);
    uint2 pk = make_uint2(*(uint32_t*)&h01, *(uint32_t*)&h23);
    *(uint2*)&g_xs[(size_t)row * FIN + lane * 4] = pk;
}

// One warp per dst node: sum fp16 x_sparse rows of neighbors in fp32.
__global__ void agg_kernel() {
    int gw = (blockIdx.x * blockDim.x + threadIdx.x) >> 5;
    int lane = threadIdx.x & 31;
    if (gw >= NN) return;
    int start = g_off[gw] + g_bsum[gw >> 10];
    int end   = g_off[gw + 1] + g_bsum[(gw + 1) >> 10];
    float4 acc = make_float4(0.f, 0.f, 0.f, 0.f);
    for (int chunk = start; chunk < end; chunk += 32) {
        int i = chunk + lane;
        int s = (i < end) ? g_csr[i] : 0;
        int m = min(32, end - chunk);
        for (int j = 0; j < m; j++) {
            int ss = __shfl_sync(0xffffffffu, s, j);
            uint2 pk = *(const uint2*)&g_xs[(size_t)ss * FIN + lane * 4];
            float2 x01 = __half22float2(*(__half2*)&pk.x);
            float2 x23 = __half22float2(*(__half2*)&pk.y);
            acc.x += x01.x; acc.y += x01.y; acc.z += x23.x; acc.w += x23.y;
        }
    }
    int deg = end - start;
    float wgt = 1.0f / (float)max(deg, 1);
    __half2 h01 = __floats2half2_rn(acc.x * wgt, acc.y * wgt);
    __half2 h23 = __floats2half2_rn(acc.z * wgt, acc.w * wgt);
    uint2 pk = make_uint2(*(uint32_t*)&h01, *(uint32_t*)&h23);
    *(uint2*)&g_agg[(size_t)gw * FIN + lane * 4] = pk;
}

// Build per-thread fp16 MMA B fragments from W (row-major [k][n]).
__global__ void wprep_kernel(const float* __restrict__ Ws, const float* __restrict__ Wn) {
    int idx = blockIdx.x * 256 + threadIdx.x;   // 0..16383
    int j    = idx & 15;
    int lane = (idx >> 4) & 31;
    int wc   = (idx >> 9) & 1;
    int ks   = (idx >> 10) & 7;
    int ph   = (idx >> 13) & 1;
    int nf = j >> 1, r = j & 1;
    int k = ks * 16 + (lane & 3) * 2 + r * 8;
    int n = wc * 64 + nf * 8 + (lane >> 2);
    const float* W = ph ? Wn : Ws;
    __half2 outp = __floats2half2_rn(W[k * 128 + n], W[(k + 1) * 128 + n]);
    ((uint32_t*)g_bf)[idx] = *(uint32_t*)&outp;
}

// ---------------- single-pass fp16 HMMA GEMM ----------------
// out = [feat | agg] @ [[W_self],[W_neigh]] + b
// 128x128 CTA tile, 8 warps x (32 x 64), K in two 128-phases.
// A fp16 in smem (ldmatrix); B direct from prebuilt gmem fragments.

#define SM_TOTAL (128 * AS * 2)   // 34,816 bytes

__global__ void __launch_bounds__(256, 2) gemm_kernel(
    const float* __restrict__ feat,
    const float* __restrict__ bself,
    float* __restrict__ out)
{
    extern __shared__ char smem[];
    uint32_t sb = smem_u32(smem);
    const int t = threadIdx.x, w = t >> 5, lane = t & 31;
    const int rowBase = blockIdx.x * 128;
    const int wm = (w & 3) * 32;        // warp row offset in tile
    const int wc = w >> 2;              // warp col half (0/1)

    float acc[2][8][4];
    #pragma unroll
    for (int mf = 0; mf < 2; mf++)
        #pragma unroll
        for (int nf = 0; nf < 8; nf++)
            #pragma unroll
            for (int e = 0; e < 4; e++) acc[mf][nf][e] = 0.f;

    const int fr = t >> 1;      // fill row 0..127
    const int half = t & 1;     // fill col half
    const int gr = rowBase + fr;
    const bool valid = gr < NN;

    #pragma unroll
    for (int ph = 0; ph < 2; ph++) {
        if (ph) __syncthreads();   // protect smem reuse from previous phase

        if (ph == 0) {
            // ---- A fill: fp32 feat -> fp16 smem ----
            #pragma unroll 4
            for (int j = 0; j < 16; j++) {
                int c = half * 64 + j * 4;
                float4 v = valid ? *(const float4*)(feat + (size_t)gr * FIN + c)
                                 : make_float4(0.f, 0.f, 0.f, 0.f);
                __half2 h01 = __floats2half2_rn(v.x, v.y);
                __half2 h23 = __floats2half2_rn(v.z, v.w);
                uint32_t o = (uint32_t)((fr * AS + c) * 2);
                *(__half2*)(smem + o)     = h01;
                *(__half2*)(smem + o + 4) = h23;
            }
        } else {
            // ---- A fill: fp16 agg, straight 16B copies ----
            #pragma unroll
            for (int j = 0; j < 8; j++) {
                int c = half * 64 + j * 8;
                uint4 v = valid ? *(const uint4*)&g_agg[(size_t)gr * FIN + c]
                                : make_uint4(0u, 0u, 0u, 0u);
                *(uint4*)(smem + (uint32_t)((fr * AS + c) * 2)) = v;
            }
        }
        __syncthreads();

        // ---- MMA mainloop: 8 k-steps of 16 ----
        #pragma unroll
        for (int ks = 0; ks < 8; ks++) {
            const int kb = ks * 16;
            // B fragments: 64B contiguous per thread, L1/L2 resident
            uint32_t bfr[16];
            {
                const uint4* hp = (const uint4*)&g_bf[ph][ks][wc][lane][0];
                #pragma unroll
                for (int q = 0; q < 4; q++) *(uint4*)&bfr[q * 4] = hp[q];
            }
            uint32_t afr[2][4];
            #pragma unroll
            for (int mf = 0; mf < 2; mf++)
                ldm_x4(afr[mf], ldm_addr(sb, wm + mf * 16, kb, lane));
            #pragma unroll
            for (int mf = 0; mf < 2; mf++)
                #pragma unroll
                for (int nf = 0; nf < 8; nf++)
                    mma_fp16(acc[mf][nf], afr[mf], bfr[nf * 2], bfr[nf * 2 + 1]);
        }
    }

    // ---- epilogue: +bias, store ----
    const int wn = wc * 64;
    const int cg = (lane & 3) * 2;     // col pair within n-frag
    const int rr = lane >> 2;          // row within m-frag half
    #pragma unroll
    for (int mf = 0; mf < 2; mf++) {
        int r0 = rowBase + wm + mf * 16 + rr;
        int r1 = r0 + 8;
        #pragma unroll
        for (int nf = 0; nf < 8; nf++) {
            int col = wn + nf * 8 + cg;
            float b0 = __ldg(bself + col), b1 = __ldg(bself + col + 1);
            if (r0 < NN) {
                float2 o = make_float2(acc[mf][nf][0] + b0, acc[mf][nf][1] + b1);
                *(float2*)(out + (size_t)r0 * FIN + col) = o;
            }
            if (r1 < NN) {
                float2 o = make_float2(acc[mf][nf][2] + b0, acc[mf][nf][3] + b1);
                *(float2*)(out + (size_t)r1 * FIN + col) = o;
            }
        }
    }
}

// ---------------- launch ----------------
extern "C" void kernel_launch(void* const* d_in, const int* in_sizes, int n_in,
                              void* d_out, int out_size) {
    const float *feat = nullptr, *topkv = nullptr, *Wself = nullptr,
                *bself = nullptr, *Wneigh = nullptr;
    const int *topki = nullptr, *src = nullptr, *dst = nullptr;

    for (int i = 0; i < n_in; i++) {
        int s = in_sizes[i];
        const void* p = d_in[i];
        if (s == NN * FIN)       feat = (const float*)p;
        else if (s == NN * KK) { if (!topkv) topkv = (const float*)p; else topki = (const int*)p; }
        else if (s == EE)      { if (!src)   src   = (const int*)p;   else dst   = (const int*)p; }
        else if (s == 128*128) { if (!Wself) Wself = (const float*)p; else Wneigh = (const float*)p; }
        else if (s == 128)       bself = (const float*)p;
    }
    float* out = (float*)d_out;

    static void* p_deg = nullptr;
    if (!p_deg) {
        cudaGetSymbolAddress(&p_deg, g_deg);
        cudaFuncSetAttribute(gemm_kernel, cudaFuncAttributeMaxDynamicSharedMemorySize, SM_TOTAL);
    }

    cudaMemsetAsync(p_deg, 0, NN * sizeof(int));
    deg_kernel<<<(EE + 255) / 256, 256>>>(dst);
    scan1_kernel<<<NB_SCAN, 1024>>>();
    scan2_kernel<<<1, 32>>>();
    scatter_kernel<<<(EE + 255) / 256, 256>>>(src, dst);
    xs_kernel<<<(NN + 7) / 8, 256>>>(topkv, topki);
    wprep_kernel<<<64, 256>>>(Wself, Wneigh);
    agg_kernel<<<(NN + 7) / 8, 256>>>();
    gemm_kernel<<<(NN + 127) / 128, 256, SM_TOTAL>>>(feat, bself, out);
}